// round 1
// baseline (speedup 1.0000x reference)
#include <cuda_runtime.h>
#include <cstdint>

// Problem shapes (fixed by setup_inputs)
#define N_NODES 100000
#define F_DIM   128
#define D_DIM   32
#define P_POOL  50000
#define L_SEQ   100
#define B_BATCH 1024
#define R_RET   5

// Scratch (no cudaMalloc allowed)
__device__ float g_proj[N_NODES * D_DIM];   // raw @ W_feat + b_feat  [N,32]
__device__ int   g_skill[N_NODES];          // (int)raw[:,0]

__device__ __forceinline__ unsigned long long pack2(float a, float b) {
    unsigned long long r;
    asm("mov.b64 %0, {%1, %2};" : "=l"(r) : "f"(a), "f"(b));
    return r;
}
__device__ __forceinline__ void unpack2(unsigned long long v, float& a, float& b) {
    asm("mov.b64 {%0, %1}, %2;" : "=f"(a), "=f"(b) : "l"(v));
}
// Packed 2-wide fp32 FMA (sm_100+): d = a*b + d
__device__ __forceinline__ void fma2(unsigned long long& d,
                                     unsigned long long a, unsigned long long b) {
    asm("fma.rn.f32x2 %0, %1, %2, %0;" : "+l"(d) : "l"(a), "l"(b));
}

// ---------------------------------------------------------------------------
// Kernel 1: proj[n,:] = raw[n,:] @ W_feat + b_feat ;  skill[n] = (int)raw[n,0]
// One row per thread; W_feat staged in shared as packed f32x2 pairs.
// ---------------------------------------------------------------------------
__global__ __launch_bounds__(256)
void proj_kernel(const float* __restrict__ raw,
                 const float* __restrict__ Wf,
                 const float* __restrict__ bf)
{
    __shared__ ulonglong2 Wsh[F_DIM * 8];   // [f][q], q=0..7, each = 2 packed pairs
    __shared__ float bfsh[D_DIM];

    // Build packed W: pair p holds (W[f][2p], W[f][2p+1])
    unsigned long long* Wsh64 = reinterpret_cast<unsigned long long*>(Wsh);
    for (int i = threadIdx.x; i < F_DIM * 16; i += 256) {
        int f = i >> 4, p = i & 15;
        Wsh64[i] = pack2(Wf[f * D_DIM + 2 * p], Wf[f * D_DIM + 2 * p + 1]);
    }
    if (threadIdx.x < D_DIM) bfsh[threadIdx.x] = bf[threadIdx.x];
    __syncthreads();

    int row = blockIdx.x * 256 + threadIdx.x;
    if (row >= N_NODES) return;

    const float4* rrow = reinterpret_cast<const float4*>(raw + (long long)row * F_DIM);

    unsigned long long acc[16];
    #pragma unroll
    for (int i = 0; i < 16; i++) acc[i] = pack2(bfsh[2 * i], bfsh[2 * i + 1]);

    int sk = 0;
    for (int f4 = 0; f4 < F_DIM / 4; f4++) {
        float4 a = rrow[f4];
        if (f4 == 0) sk = (int)a.x;
        float av[4] = {a.x, a.y, a.z, a.w};
        #pragma unroll
        for (int j = 0; j < 4; j++) {
            int f = f4 * 4 + j;
            unsigned long long ap = pack2(av[j], av[j]);
            #pragma unroll
            for (int q = 0; q < 8; q++) {
                ulonglong2 w = Wsh[f * 8 + q];   // one LDS.128 -> two packed pairs
                fma2(acc[q * 2 + 0], ap, w.x);
                fma2(acc[q * 2 + 1], ap, w.y);
            }
        }
    }

    float* out = g_proj + (long long)row * D_DIM;
    #pragma unroll
    for (int i = 0; i < 16; i++) {
        float lo, hi;
        unpack2(acc[i], lo, hi);
        out[2 * i] = lo;
        out[2 * i + 1] = hi;
    }
    g_skill[row] = sk;
}

// ---------------------------------------------------------------------------
// Kernel 2: per-batch fused pipeline. One block per b, 256 threads (8 warps).
//   hist[l] = mean_r proj[node] + (mean_r sim)*w_struct + b_struct  -> LayerNorm
//   xW = hist @ W_gcn ; chain-GCN closed form ; relu ; mean-pool over L
//   src_emb = pool @ W_out + b_out ; dst_emb = proj[dst] @ W_out + b_out
// ---------------------------------------------------------------------------
__global__ __launch_bounds__(256)
void main_kernel(const int* __restrict__ retrieved_nodes,    // [P,L]
                 const int* __restrict__ retrieved_indices,  // [B,R]
                 const int* __restrict__ dst_node_ids,       // [B]
                 const float* __restrict__ w_struct, const float* __restrict__ b_struct,
                 const float* __restrict__ ln_g,    const float* __restrict__ ln_b,
                 const float* __restrict__ W_gcn,   const float* __restrict__ b_gcn,
                 const float* __restrict__ W_out,   const float* __restrict__ b_out,
                 float* __restrict__ out)
{
    __shared__ float hist[L_SEQ][D_DIM];
    __shared__ float xw[L_SEQ][D_DIM];
    __shared__ float Wg[D_DIM * D_DIM];
    __shared__ float Wo[D_DIM * D_DIM];
    __shared__ float ws[D_DIM], bs[D_DIM], lg[D_DIM], lb[D_DIM], bg[D_DIM], bo[D_DIM];
    __shared__ float partial[8][D_DIM];
    __shared__ float dstfeat[D_DIM];
    __shared__ int   pidx[R_RET];
    __shared__ int   validsh;
    __shared__ int   curskill;

    const int b = blockIdx.x;
    const int tid = threadIdx.x;
    const int warp = tid >> 5;
    const int lane = tid & 31;

    for (int i = tid; i < D_DIM * D_DIM; i += 256) { Wg[i] = W_gcn[i]; Wo[i] = W_out[i]; }
    if (tid < D_DIM) {
        ws[tid] = w_struct[tid]; bs[tid] = b_struct[tid];
        lg[tid] = ln_g[tid];     lb[tid] = ln_b[tid];
        bg[tid] = b_gcn[tid];    bo[tid] = b_out[tid];
    }
    if (tid < R_RET) pidx[tid] = retrieved_indices[b * R_RET + tid];
    if (tid == 0) {
        validsh = 0;
        curskill = g_skill[dst_node_ids[b]];
    }
    if (tid >= 32 && tid < 64)
        dstfeat[tid - 32] = g_proj[(long long)dst_node_ids[b] * D_DIM + (tid - 32)];
    __syncthreads();

    const int cs = curskill;

    // ---- hist + LayerNorm (warp per l, lane = channel) ----
    for (int l = warp; l < L_SEQ; l += 8) {
        float s = 0.f;
        int simc = 0, n0 = 0;
        #pragma unroll
        for (int r = 0; r < R_RET; r++) {
            int n = retrieved_nodes[pidx[r] * L_SEQ + l];
            if (r == 0) n0 = n;
            s += g_proj[(long long)n * D_DIM + lane];
            simc += (g_skill[n] == cs) ? 1 : 0;
        }
        float val = s * 0.2f + ((float)simc * 0.2f) * ws[lane] + bs[lane];
        if (lane == 0) atomicAdd(&validsh, (n0 > 0) ? 1 : 0);

        float m = val;
        #pragma unroll
        for (int o = 16; o; o >>= 1) m += __shfl_xor_sync(0xffffffffu, m, o);
        m *= (1.f / 32.f);
        float dv = val - m;
        float v = dv * dv;
        #pragma unroll
        for (int o = 16; o; o >>= 1) v += __shfl_xor_sync(0xffffffffu, v, o);
        v *= (1.f / 32.f);
        hist[l][lane] = dv * rsqrtf(v + 1e-5f) * lg[lane] + lb[lane];
    }
    __syncthreads();
    const int valid = validsh;

    // ---- xW = hist @ W_gcn ----
    for (int l = warp; l < L_SEQ; l += 8) {
        float acc = 0.f;
        #pragma unroll
        for (int k = 0; k < D_DIM; k++) acc = fmaf(hist[l][k], Wg[k * D_DIM + lane], acc);
        xw[l][lane] = acc;
    }
    __syncthreads();

    // ---- chain GCN + relu + mean pool (deterministic tree reduce) ----
    // deg[0]=1 ; deg[l]=1+(l<valid) for l>=1 ; edge into l iff (l>=1 && l<valid)
    float pacc = 0.f;
    for (int l = warp; l < L_SEQ; l += 8) {
        float degl = (l >= 1 && l < valid) ? 2.f : 1.f;
        float o = xw[l][lane] / degl;
        if (l >= 1 && l < valid) {
            float degp = (l - 1 >= 1 && (l - 1) < valid) ? 2.f : 1.f;
            o += xw[l - 1][lane] * rsqrtf(degp * degl);
        }
        o += bg[lane];
        pacc += fmaxf(o, 0.f);
    }
    partial[warp][lane] = pacc;
    __syncthreads();

    if (warp == 0) {
        float p = 0.f;
        #pragma unroll
        for (int w = 0; w < 8; w++) p += partial[w][lane];
        partial[0][lane] = p * (1.f / (float)L_SEQ);
    }
    __syncthreads();

    if (warp == 0) {
        // src_emb = pool @ W_out + b_out
        float acc = bo[lane];
        #pragma unroll
        for (int k = 0; k < D_DIM; k++) acc = fmaf(partial[0][k], Wo[k * D_DIM + lane], acc);
        out[b * D_DIM + lane] = acc;
    } else if (warp == 1) {
        // dst_emb = proj[dst] @ W_out + b_out
        float acc = bo[lane];
        #pragma unroll
        for (int k = 0; k < D_DIM; k++) acc = fmaf(dstfeat[k], Wo[k * D_DIM + lane], acc);
        out[B_BATCH * D_DIM + b * D_DIM + lane] = acc;
    }
}

// ---------------------------------------------------------------------------
extern "C" void kernel_launch(void* const* d_in, const int* in_sizes, int n_in,
                              void* d_out, int out_size)
{
    const float* raw      = (const float*)d_in[0];   // [N,F]
    const int*   rnodes   = (const int*)  d_in[1];   // [P,L]
    const int*   rindices = (const int*)  d_in[2];   // [B,R]
    // d_in[3] = src_node_ids (unused by reference)
    const int*   dst_ids  = (const int*)  d_in[4];   // [B]
    // d_in[5] = node_interact_times (unused)
    const float* W_feat   = (const float*)d_in[6];
    const float* b_feat   = (const float*)d_in[7];
    const float* w_struct = (const float*)d_in[8];
    const float* b_struct = (const float*)d_in[9];
    const float* ln_g     = (const float*)d_in[10];
    const float* ln_b     = (const float*)d_in[11];
    const float* W_gcn    = (const float*)d_in[12];
    const float* b_gcn    = (const float*)d_in[13];
    const float* W_out    = (const float*)d_in[14];
    const float* b_out    = (const float*)d_in[15];
    float* out = (float*)d_out;

    proj_kernel<<<(N_NODES + 255) / 256, 256>>>(raw, W_feat, b_feat);
    main_kernel<<<B_BATCH, 256>>>(rnodes, rindices, dst_ids,
                                  w_struct, b_struct, ln_g, ln_b,
                                  W_gcn, b_gcn, W_out, b_out, out);
}

// round 2
// speedup vs baseline: 1.2012x; 1.2012x over previous
#include <cuda_runtime.h>
#include <cstdint>

#define N_NODES 100000
#define F_DIM   128
#define D_DIM   32
#define L_SEQ   100
#define B_BATCH 1024
#define R_RET   5
#define ROWS_PB 128   // rows per proj block

__device__ float g_proj[N_NODES * D_DIM];
__device__ int   g_skill[N_NODES];

__device__ __forceinline__ unsigned long long pack2(float a, float b) {
    unsigned long long r;
    asm("mov.b64 %0, {%1, %2};" : "=l"(r) : "f"(a), "f"(b));
    return r;
}
__device__ __forceinline__ void unpack2(unsigned long long v, float& a, float& b) {
    asm("mov.b64 {%0, %1}, %2;" : "=f"(a), "=f"(b) : "l"(v));
}
// packed 2-wide fp32 FMA: d = a*b + d
__device__ __forceinline__ void fma2(unsigned long long& d,
                                     unsigned long long a, unsigned long long b) {
    asm("fma.rn.f32x2 %0, %1, %2, %0;" : "+l"(d) : "l"(a), "l"(b));
}

// ---------------------------------------------------------------------------
// proj[n,:] = raw[n,:] @ W_feat + b_feat ; skill[n] = (int)raw[n,0]
// Block = 256 threads, 128 rows. A-tile staged in smem (coalesced loads,
// stride-129 padding). Thread = (row, half): 16 outputs as 8 FMA2 accs.
// Outputs staged back through smem for coalesced STG.128.
// ---------------------------------------------------------------------------
__global__ __launch_bounds__(256)
void proj_kernel(const float* __restrict__ raw,
                 const float* __restrict__ Wf,
                 const float* __restrict__ bf)
{
    __shared__ float      Ash[ROWS_PB * 129];   // 66048 B (reused for out staging)
    __shared__ ulonglong2 Wsh[F_DIM * 8];       // 16 KB packed pairs
    __shared__ float      bfsh[D_DIM];

    const int tid = threadIdx.x;

    // pack W: u64 #p of row f holds (W[f][2p], W[f][2p+1])
    unsigned long long* W64 = reinterpret_cast<unsigned long long*>(Wsh);
    for (int i = tid; i < F_DIM * 16; i += 256) {
        int f = i >> 4, p = i & 15;
        W64[i] = pack2(Wf[f * D_DIM + 2 * p], Wf[f * D_DIM + 2 * p + 1]);
    }
    if (tid < D_DIM) bfsh[tid] = bf[tid];

    const int rowBase = blockIdx.x * ROWS_PB;

    // coalesced A-tile load: 128 rows x 128 floats
    {
        const float4* g = reinterpret_cast<const float4*>(raw + (size_t)rowBase * F_DIM);
        for (int i = tid; i < ROWS_PB * 32; i += 256) {
            int r = i >> 5, c4 = i & 31;
            float4 v = make_float4(0.f, 0.f, 0.f, 0.f);
            if (rowBase + r < N_NODES) v = g[i];
            float* dst = Ash + r * 129 + c4 * 4;
            dst[0] = v.x; dst[1] = v.y; dst[2] = v.z; dst[3] = v.w;
        }
    }
    __syncthreads();

    const int rowL = tid >> 1;         // local row 0..127
    const int half = tid & 1;          // output half: [half*16, half*16+16)
    const float* arow = Ash + rowL * 129;

    unsigned long long acc[8];
    #pragma unroll
    for (int q = 0; q < 8; q++)
        acc[q] = pack2(bfsh[half * 16 + 2 * q], bfsh[half * 16 + 2 * q + 1]);

    #pragma unroll 4
    for (int f = 0; f < F_DIM; f++) {
        float a = arow[f];
        unsigned long long ap = pack2(a, a);
        ulonglong2 w0 = Wsh[f * 8 + half * 4 + 0];
        ulonglong2 w1 = Wsh[f * 8 + half * 4 + 1];
        ulonglong2 w2 = Wsh[f * 8 + half * 4 + 2];
        ulonglong2 w3 = Wsh[f * 8 + half * 4 + 3];
        fma2(acc[0], ap, w0.x); fma2(acc[1], ap, w0.y);
        fma2(acc[2], ap, w1.x); fma2(acc[3], ap, w1.y);
        fma2(acc[4], ap, w2.x); fma2(acc[5], ap, w2.y);
        fma2(acc[6], ap, w3.x); fma2(acc[7], ap, w3.y);
    }

    float a0 = arow[0];                 // for skill, before Ash is reused
    __syncthreads();

    // stage outputs: row-major [128][33] into Ash region (conflict-free)
    #pragma unroll
    for (int q = 0; q < 8; q++) {
        float lo, hi;
        unpack2(acc[q], lo, hi);
        Ash[rowL * 33 + half * 16 + 2 * q]     = lo;
        Ash[rowL * 33 + half * 16 + 2 * q + 1] = hi;
    }
    if (half == 0 && rowBase + rowL < N_NODES)
        g_skill[rowBase + rowL] = (int)a0;
    __syncthreads();

    // coalesced store: 128 rows x 8 float4
    float4* gout = reinterpret_cast<float4*>(g_proj + (size_t)rowBase * D_DIM);
    for (int i = tid; i < ROWS_PB * 8; i += 256) {
        int r = i >> 3, c4 = i & 7;
        if (rowBase + r < N_NODES) {
            const float* s = Ash + r * 33 + c4 * 4;
            gout[i] = make_float4(s[0], s[1], s[2], s[3]);
        }
    }
}

// ---------------------------------------------------------------------------
// Per-batch fused pipeline: one block per b, 256 threads (8 warps).
// Node ids preloaded to smem; gathers issued 20-wide per warp iteration.
// ---------------------------------------------------------------------------
__global__ __launch_bounds__(256)
void main_kernel(const int* __restrict__ retrieved_nodes,    // [P,L]
                 const int* __restrict__ retrieved_indices,  // [B,R]
                 const int* __restrict__ dst_node_ids,       // [B]
                 const float* __restrict__ w_struct, const float* __restrict__ b_struct,
                 const float* __restrict__ ln_g,    const float* __restrict__ ln_b,
                 const float* __restrict__ W_gcn,   const float* __restrict__ b_gcn,
                 const float* __restrict__ W_out,   const float* __restrict__ b_out,
                 float* __restrict__ out)
{
    __shared__ float hist[L_SEQ][D_DIM];
    __shared__ float xw[L_SEQ][D_DIM];
    __shared__ float Wg[D_DIM * D_DIM];
    __shared__ float Wo[D_DIM * D_DIM];
    __shared__ float ws[D_DIM], bs[D_DIM], lg[D_DIM], lb[D_DIM], bg[D_DIM], bo[D_DIM];
    __shared__ float partial[8][D_DIM];
    __shared__ float dstfeat[D_DIM];
    __shared__ int   nodes_sh[R_RET][L_SEQ];
    __shared__ int   pidx[R_RET];
    __shared__ int   validsh;
    __shared__ int   curskill;

    const int b = blockIdx.x;
    const int tid = threadIdx.x;
    const int warp = tid >> 5;
    const int lane = tid & 31;

    for (int i = tid; i < D_DIM * D_DIM; i += 256) { Wg[i] = W_gcn[i]; Wo[i] = W_out[i]; }
    if (tid < D_DIM) {
        ws[tid] = w_struct[tid]; bs[tid] = b_struct[tid];
        lg[tid] = ln_g[tid];     lb[tid] = ln_b[tid];
        bg[tid] = b_gcn[tid];    bo[tid] = b_out[tid];
    }
    if (tid < R_RET) pidx[tid] = retrieved_indices[b * R_RET + tid];
    if (tid == 0) {
        validsh = 0;
        curskill = g_skill[dst_node_ids[b]];
    }
    if (tid >= 32 && tid < 64)
        dstfeat[tid - 32] = g_proj[(size_t)dst_node_ids[b] * D_DIM + (tid - 32)];
    __syncthreads();

    // node ids: one warp per retrieval row, coalesced
    if (warp < R_RET) {
        const int* src = retrieved_nodes + (size_t)pidx[warp] * L_SEQ;
        for (int l = lane; l < L_SEQ; l += 32) nodes_sh[warp][l] = src[l];
    }
    __syncthreads();

    if (tid < L_SEQ && nodes_sh[0][tid] > 0) atomicAdd(&validsh, 1);

    const int cs = curskill;

    // ---- hist + LayerNorm: warp per l, lane = channel, 2 l's in flight ----
    for (int l0 = warp; l0 < L_SEQ; l0 += 16) {
        const int l1 = l0 + 8;
        const bool has1 = (l1 < L_SEQ);

        float p0[R_RET], p1[R_RET];
        int   s0[R_RET], s1[R_RET];
        #pragma unroll
        for (int r = 0; r < R_RET; r++) {
            int n = nodes_sh[r][l0];
            p0[r] = g_proj[(size_t)n * D_DIM + lane];
            s0[r] = g_skill[n];
        }
        if (has1) {
            #pragma unroll
            for (int r = 0; r < R_RET; r++) {
                int n = nodes_sh[r][l1];
                p1[r] = g_proj[(size_t)n * D_DIM + lane];
                s1[r] = g_skill[n];
            }
        }

        {
            float s = p0[0] + p0[1] + p0[2] + p0[3] + p0[4];
            int simc = (s0[0]==cs) + (s0[1]==cs) + (s0[2]==cs) + (s0[3]==cs) + (s0[4]==cs);
            float val = s * 0.2f + ((float)simc * 0.2f) * ws[lane] + bs[lane];
            float m = val;
            #pragma unroll
            for (int o = 16; o; o >>= 1) m += __shfl_xor_sync(0xffffffffu, m, o);
            m *= (1.f / 32.f);
            float dv = val - m;
            float v = dv * dv;
            #pragma unroll
            for (int o = 16; o; o >>= 1) v += __shfl_xor_sync(0xffffffffu, v, o);
            v *= (1.f / 32.f);
            hist[l0][lane] = dv * rsqrtf(v + 1e-5f) * lg[lane] + lb[lane];
        }
        if (has1) {
            float s = p1[0] + p1[1] + p1[2] + p1[3] + p1[4];
            int simc = (s1[0]==cs) + (s1[1]==cs) + (s1[2]==cs) + (s1[3]==cs) + (s1[4]==cs);
            float val = s * 0.2f + ((float)simc * 0.2f) * ws[lane] + bs[lane];
            float m = val;
            #pragma unroll
            for (int o = 16; o; o >>= 1) m += __shfl_xor_sync(0xffffffffu, m, o);
            m *= (1.f / 32.f);
            float dv = val - m;
            float v = dv * dv;
            #pragma unroll
            for (int o = 16; o; o >>= 1) v += __shfl_xor_sync(0xffffffffu, v, o);
            v *= (1.f / 32.f);
            hist[l1][lane] = dv * rsqrtf(v + 1e-5f) * lg[lane] + lb[lane];
        }
    }
    __syncthreads();
    const int valid = validsh;

    // ---- xW = hist @ W_gcn ----
    for (int l = warp; l < L_SEQ; l += 8) {
        float acc = 0.f;
        #pragma unroll
        for (int k = 0; k < D_DIM; k++) acc = fmaf(hist[l][k], Wg[k * D_DIM + lane], acc);
        xw[l][lane] = acc;
    }
    __syncthreads();

    // ---- chain GCN + relu + mean pool ----
    float pacc = 0.f;
    for (int l = warp; l < L_SEQ; l += 8) {
        float degl = (l >= 1 && l < valid) ? 2.f : 1.f;
        float o = xw[l][lane] / degl;
        if (l >= 1 && l < valid) {
            float degp = (l - 1 >= 1 && (l - 1) < valid) ? 2.f : 1.f;
            o += xw[l - 1][lane] * rsqrtf(degp * degl);
        }
        o += bg[lane];
        pacc += fmaxf(o, 0.f);
    }
    partial[warp][lane] = pacc;
    __syncthreads();

    if (warp == 0) {
        float p = 0.f;
        #pragma unroll
        for (int w = 0; w < 8; w++) p += partial[w][lane];
        partial[0][lane] = p * (1.f / (float)L_SEQ);
    }
    __syncthreads();

    if (warp == 0) {
        float acc = bo[lane];
        #pragma unroll
        for (int k = 0; k < D_DIM; k++) acc = fmaf(partial[0][k], Wo[k * D_DIM + lane], acc);
        out[b * D_DIM + lane] = acc;
    } else if (warp == 1) {
        float acc = bo[lane];
        #pragma unroll
        for (int k = 0; k < D_DIM; k++) acc = fmaf(dstfeat[k], Wo[k * D_DIM + lane], acc);
        out[B_BATCH * D_DIM + b * D_DIM + lane] = acc;
    }
}

// ---------------------------------------------------------------------------
extern "C" void kernel_launch(void* const* d_in, const int* in_sizes, int n_in,
                              void* d_out, int out_size)
{
    const float* raw      = (const float*)d_in[0];
    const int*   rnodes   = (const int*)  d_in[1];
    const int*   rindices = (const int*)  d_in[2];
    const int*   dst_ids  = (const int*)  d_in[4];
    const float* W_feat   = (const float*)d_in[6];
    const float* b_feat   = (const float*)d_in[7];
    const float* w_struct = (const float*)d_in[8];
    const float* b_struct = (const float*)d_in[9];
    const float* ln_g     = (const float*)d_in[10];
    const float* ln_b     = (const float*)d_in[11];
    const float* W_gcn    = (const float*)d_in[12];
    const float* b_gcn    = (const float*)d_in[13];
    const float* W_out    = (const float*)d_in[14];
    const float* b_out    = (const float*)d_in[15];
    float* out = (float*)d_out;

    proj_kernel<<<(N_NODES + ROWS_PB - 1) / ROWS_PB, 256>>>(raw, W_feat, b_feat);
    main_kernel<<<B_BATCH, 256>>>(rnodes, rindices, dst_ids,
                                  w_struct, b_struct, ln_g, ln_b,
                                  W_gcn, b_gcn, W_out, b_out, out);
}

// round 7
// speedup vs baseline: 1.3251x; 1.1032x over previous
#include <cuda_runtime.h>
#include <cstdint>

#define N_NODES 100000
#define F_DIM   128
#define D_DIM   32
#define L_SEQ   100
#define B_BATCH 1024
#define R_RET   5
#define ROWS_PB 128
#define KCH     32          // K-chunk for proj pipeline
#define NCH     (F_DIM / KCH)

__device__ float g_proj[N_NODES * D_DIM];
__device__ int   g_skill[N_NODES];

__device__ __forceinline__ unsigned long long pack2(float a, float b) {
    unsigned long long r;
    asm("mov.b64 %0, {%1, %2};" : "=l"(r) : "f"(a), "f"(b));
    return r;
}
__device__ __forceinline__ void unpack2(unsigned long long v, float& a, float& b) {
    asm("mov.b64 {%0, %1}, %2;" : "=f"(a), "=f"(b) : "l"(v));
}
__device__ __forceinline__ void fma2(unsigned long long& d,
                                     unsigned long long a, unsigned long long b) {
    asm("fma.rn.f32x2 %0, %1, %2, %0;" : "+l"(d) : "l"(a), "l"(b));
}

// ---------------------------------------------------------------------------
// proj[n,:] = raw[n,:] @ W_feat + b_feat ; skill[n] = (int)raw[n,0]
// K-chunked, double-buffered smem, register-staged prefetch, FMA2 inner loop.
// ---------------------------------------------------------------------------
__global__ __launch_bounds__(256)
void proj_kernel(const float* __restrict__ raw,
                 const float* __restrict__ Wf,
                 const float* __restrict__ bf)
{
    __shared__ float      Ash[2][ROWS_PB * 33];     // 33.8 KB, conflict-free
    __shared__ ulonglong2 Wsh[F_DIM * 8];           // 16 KB packed W pairs
    __shared__ float      bfsh[D_DIM];

    const int tid = threadIdx.x;
    const int rowBase = blockIdx.x * ROWS_PB;

    // pack W: u64 #p of row f = (W[f][2p], W[f][2p+1])
    unsigned long long* W64 = reinterpret_cast<unsigned long long*>(Wsh);
    for (int i = tid; i < F_DIM * 16; i += 256) {
        int f = i >> 4, p = i & 15;
        W64[i] = pack2(Wf[f * D_DIM + 2 * p], Wf[f * D_DIM + 2 * p + 1]);
    }
    if (tid < D_DIM) bfsh[tid] = bf[tid];

    // chunk load: 128 rows x 32 floats = 1024 float4; thread does 4
    float4 R[4];
    auto ldg_chunk = [&](int ch) {
        #pragma unroll
        for (int j = 0; j < 4; j++) {
            int v = tid + j * 256;           // float4 index in chunk
            int r = v >> 3, c4 = v & 7;
            float4 val = make_float4(0.f, 0.f, 0.f, 0.f);
            if (rowBase + r < N_NODES)
                val = *reinterpret_cast<const float4*>(
                    raw + (size_t)(rowBase + r) * F_DIM + ch * KCH + c4 * 4);
            R[j] = val;
        }
    };
    auto sts_chunk = [&](int buf) {
        #pragma unroll
        for (int j = 0; j < 4; j++) {
            int v = tid + j * 256;
            int r = v >> 3, c4 = v & 7;
            float* d = &Ash[buf][r * 33 + c4 * 4];
            d[0] = R[j].x; d[1] = R[j].y; d[2] = R[j].z; d[3] = R[j].w;
        }
    };

    const int rowL = tid >> 1;
    const int half = tid & 1;

    ldg_chunk(0);
    sts_chunk(0);
    __syncthreads();   // fences bfsh + Wsh + chunk 0 for ALL threads

    // acc init AFTER the barrier (bfsh written only by tid<32 — R5 bug was here)
    unsigned long long acc[8];
    #pragma unroll
    for (int q = 0; q < 8; q++)
        acc[q] = pack2(bfsh[half * 16 + 2 * q], bfsh[half * 16 + 2 * q + 1]);

    float a0 = Ash[0][rowL * 33];   // raw[row][0] for skill

    #pragma unroll
    for (int ch = 0; ch < NCH; ch++) {
        const int buf = ch & 1;
        if (ch + 1 < NCH) ldg_chunk(ch + 1);          // overlap with compute

        const float* arow = &Ash[buf][rowL * 33];
        const ulonglong2* wb = &Wsh[(size_t)ch * KCH * 8 + half * 4];
        #pragma unroll 4
        for (int f = 0; f < KCH; f++) {
            float a = arow[f];
            unsigned long long ap = pack2(a, a);
            ulonglong2 w0 = wb[f * 8 + 0];
            ulonglong2 w1 = wb[f * 8 + 1];
            ulonglong2 w2 = wb[f * 8 + 2];
            ulonglong2 w3 = wb[f * 8 + 3];
            fma2(acc[0], ap, w0.x); fma2(acc[1], ap, w0.y);
            fma2(acc[2], ap, w1.x); fma2(acc[3], ap, w1.y);
            fma2(acc[4], ap, w2.x); fma2(acc[5], ap, w2.y);
            fma2(acc[6], ap, w3.x); fma2(acc[7], ap, w3.y);
        }
        if (ch + 1 < NCH) sts_chunk(buf ^ 1);
        __syncthreads();
    }

    // direct stores: 4x STG.128 per thread
    if (rowBase + rowL < N_NODES) {
        float* out = g_proj + (size_t)(rowBase + rowL) * D_DIM + half * 16;
        #pragma unroll
        for (int q = 0; q < 4; q++) {
            float lo0, hi0, lo1, hi1;
            unpack2(acc[2 * q], lo0, hi0);
            unpack2(acc[2 * q + 1], lo1, hi1);
            *reinterpret_cast<float4*>(out + 4 * q) = make_float4(lo0, hi0, lo1, hi1);
        }
        if (half == 0) g_skill[rowBase + rowL] = (int)a0;
    }
}

// ---------------------------------------------------------------------------
// Per-batch fused pipeline: one block per b, 256 threads (8 warps).
// W_gcn hoisted to registers; LN single-pass with interleaved shuffle trees.
// ---------------------------------------------------------------------------
__global__ __launch_bounds__(256)
void main_kernel(const int* __restrict__ retrieved_nodes,    // [P,L]
                 const int* __restrict__ retrieved_indices,  // [B,R]
                 const int* __restrict__ dst_node_ids,       // [B]
                 const float* __restrict__ w_struct, const float* __restrict__ b_struct,
                 const float* __restrict__ ln_g,    const float* __restrict__ ln_b,
                 const float* __restrict__ W_gcn,   const float* __restrict__ b_gcn,
                 const float* __restrict__ W_out,   const float* __restrict__ b_out,
                 float* __restrict__ out)
{
    __shared__ float hist[L_SEQ][D_DIM];
    __shared__ float xw[L_SEQ][D_DIM];
    __shared__ float ws[D_DIM], bs[D_DIM], lg[D_DIM], lb[D_DIM], bg[D_DIM];
    __shared__ float partial[8][D_DIM];
    __shared__ float dstfeat[D_DIM];
    __shared__ int   nodes_sh[R_RET][L_SEQ];
    __shared__ int   pidx[R_RET];
    __shared__ int   validsh;
    __shared__ int   curskill;

    const int b = blockIdx.x;
    const int tid = threadIdx.x;
    const int warp = tid >> 5;
    const int lane = tid & 31;

    if (tid < D_DIM) {
        ws[tid] = w_struct[tid]; bs[tid] = b_struct[tid];
        lg[tid] = ln_g[tid];     lb[tid] = ln_b[tid];
        bg[tid] = b_gcn[tid];
    }
    if (tid < R_RET) pidx[tid] = retrieved_indices[b * R_RET + tid];
    if (tid == 0) {
        validsh = 0;
        curskill = g_skill[dst_node_ids[b]];
    }
    if (tid >= 32 && tid < 64)
        dstfeat[tid - 32] = g_proj[(size_t)dst_node_ids[b] * D_DIM + (tid - 32)];
    __syncthreads();

    if (warp < R_RET) {
        const int* src = retrieved_nodes + (size_t)pidx[warp] * L_SEQ;
        for (int l = lane; l < L_SEQ; l += 32) nodes_sh[warp][l] = src[l];
    }
    __syncthreads();

    if (tid < L_SEQ && nodes_sh[0][tid] > 0) atomicAdd(&validsh, 1);

    const int cs = curskill;
    const float wsl = ws[lane], bsl = bs[lane], lgl = lg[lane], lbl = lb[lane];

    // single-pass LN: interleaved sum / sum2 shuffle trees
    auto layernorm = [&](float val) -> float {
        float s1 = val, s2 = val * val;
        #pragma unroll
        for (int o = 16; o; o >>= 1) {
            s1 += __shfl_xor_sync(0xffffffffu, s1, o);
            s2 += __shfl_xor_sync(0xffffffffu, s2, o);
        }
        float mean = s1 * (1.f / 32.f);
        float var  = s2 * (1.f / 32.f) - mean * mean;
        return (val - mean) * rsqrtf(var + 1e-5f) * lgl + lbl;
    };

    // ---- hist + LayerNorm: warp per l, lane = channel, 2 l in flight ----
    for (int l0 = warp; l0 < L_SEQ; l0 += 16) {
        const int l1 = l0 + 8;
        const bool has1 = (l1 < L_SEQ);

        float p0[R_RET], p1[R_RET];
        int   s0[R_RET], s1i[R_RET];
        #pragma unroll
        for (int r = 0; r < R_RET; r++) {
            int n = nodes_sh[r][l0];
            p0[r] = g_proj[(size_t)n * D_DIM + lane];
            s0[r] = g_skill[n];
        }
        if (has1) {
            #pragma unroll
            for (int r = 0; r < R_RET; r++) {
                int n = nodes_sh[r][l1];
                p1[r] = g_proj[(size_t)n * D_DIM + lane];
                s1i[r] = g_skill[n];
            }
        }
        {
            float s = p0[0] + p0[1] + p0[2] + p0[3] + p0[4];
            int simc = (s0[0]==cs) + (s0[1]==cs) + (s0[2]==cs) + (s0[3]==cs) + (s0[4]==cs);
            float val = s * 0.2f + ((float)simc * 0.2f) * wsl + bsl;
            hist[l0][lane] = layernorm(val);
        }
        if (has1) {
            float s = p1[0] + p1[1] + p1[2] + p1[3] + p1[4];
            int simc = (s1i[0]==cs) + (s1i[1]==cs) + (s1i[2]==cs) + (s1i[3]==cs) + (s1i[4]==cs);
            float val = s * 0.2f + ((float)simc * 0.2f) * wsl + bsl;
            hist[l1][lane] = layernorm(val);
        }
    }

    // ---- hoist W_gcn column into registers (L2-resident, coalesced) ----
    float wreg[D_DIM];
    #pragma unroll
    for (int k = 0; k < D_DIM; k++) wreg[k] = W_gcn[k * D_DIM + lane];

    __syncthreads();
    const int valid = validsh;

    // ---- xW = hist @ W_gcn : 8x LDS.128 broadcast + 32 FMA per l ----
    for (int l = warp; l < L_SEQ; l += 8) {
        const float4* hp = reinterpret_cast<const float4*>(hist[l]);
        float acc = 0.f;
        #pragma unroll
        for (int q = 0; q < 8; q++) {
            float4 h = hp[q];
            acc = fmaf(h.x, wreg[4 * q + 0], acc);
            acc = fmaf(h.y, wreg[4 * q + 1], acc);
            acc = fmaf(h.z, wreg[4 * q + 2], acc);
            acc = fmaf(h.w, wreg[4 * q + 3], acc);
        }
        xw[l][lane] = acc;
    }
    __syncthreads();

    // ---- chain GCN + relu + mean pool ----
    const float bgl = bg[lane];
    float pacc = 0.f;
    for (int l = warp; l < L_SEQ; l += 8) {
        float degl = (l >= 1 && l < valid) ? 2.f : 1.f;
        float o = xw[l][lane] / degl;
        if (l >= 1 && l < valid) {
            float degp = (l - 1 >= 1 && (l - 1) < valid) ? 2.f : 1.f;
            o += xw[l - 1][lane] * rsqrtf(degp * degl);
        }
        o += bgl;
        pacc += fmaxf(o, 0.f);
    }
    partial[warp][lane] = pacc;
    __syncthreads();

    if (warp == 0) {
        float p = 0.f;
        #pragma unroll
        for (int w = 0; w < 8; w++) p += partial[w][lane];
        partial[0][lane] = p * (1.f / (float)L_SEQ);
    }
    __syncthreads();

    if (warp == 0) {
        float acc = b_out[lane];
        #pragma unroll
        for (int k = 0; k < D_DIM; k++)
            acc = fmaf(partial[0][k], W_out[k * D_DIM + lane], acc);
        out[b * D_DIM + lane] = acc;
    } else if (warp == 1) {
        float acc = b_out[lane];
        #pragma unroll
        for (int k = 0; k < D_DIM; k++)
            acc = fmaf(dstfeat[k], W_out[k * D_DIM + lane], acc);
        out[B_BATCH * D_DIM + b * D_DIM + lane] = acc;
    }
}

// ---------------------------------------------------------------------------
extern "C" void kernel_launch(void* const* d_in, const int* in_sizes, int n_in,
                              void* d_out, int out_size)
{
    const float* raw      = (const float*)d_in[0];
    const int*   rnodes   = (const int*)  d_in[1];
    const int*   rindices = (const int*)  d_in[2];
    const int*   dst_ids  = (const int*)  d_in[4];
    const float* W_feat   = (const float*)d_in[6];
    const float* b_feat   = (const float*)d_in[7];
    const float* w_struct = (const float*)d_in[8];
    const float* b_struct = (const float*)d_in[9];
    const float* ln_g     = (const float*)d_in[10];
    const float* ln_b     = (const float*)d_in[11];
    const float* W_gcn    = (const float*)d_in[12];
    const float* b_gcn    = (const float*)d_in[13];
    const float* W_out    = (const float*)d_in[14];
    const float* b_out    = (const float*)d_in[15];
    float* out = (float*)d_out;

    proj_kernel<<<(N_NODES + ROWS_PB - 1) / ROWS_PB, 256>>>(raw, W_feat, b_feat);
    main_kernel<<<B_BATCH, 256>>>(rnodes, rindices, dst_ids,
                                  w_struct, b_struct, ln_g, ln_b,
                                  W_gcn, b_gcn, W_out, b_out, out);
}

// round 9
// speedup vs baseline: 1.7943x; 1.3541x over previous
#include <cuda_runtime.h>
#include <cuda_bf16.h>
#include <cstdint>

#define N_NODES 100000
#define F_DIM   128
#define D_DIM   32
#define L_SEQ   100
#define B_BATCH 1024
#define R_RET   5
#define ROWS_PB 128
#define N_PBLK  ((N_NODES + ROWS_PB - 1) / ROWS_PB)   // 782

// smem tile layout (dynamic): bf16 rows, stride 272B (136 bf16) -> conflict-free
#define A_STRIDE 272
#define SM_AHI   0
#define SM_ALO   34816          // 128*272
#define SM_WHI   69632
#define SM_WLO   78336          // +32*272
#define SM_DYN   87040

__device__ float g_proj[N_NODES * D_DIM];
__device__ int   g_skill[N_NODES];

// pack two f32 -> bf16x2, first arg ends up in LOW 16 bits
__device__ __forceinline__ uint32_t packbf(float lo, float hi) {
    uint32_t r;
    asm("cvt.rn.bf16x2.f32 %0, %1, %2;" : "=r"(r) : "f"(hi), "f"(lo));
    return r;
}

// m16n8k16 row.col bf16 -> f32 accumulate
__device__ __forceinline__ void mma16816(float* d, const uint32_t* a, const uint32_t* b) {
    asm volatile(
        "mma.sync.aligned.m16n8k16.row.col.f32.bf16.bf16.f32 "
        "{%0,%1,%2,%3}, {%4,%5,%6,%7}, {%8,%9}, {%0,%1,%2,%3};\n"
        : "+f"(d[0]), "+f"(d[1]), "+f"(d[2]), "+f"(d[3])
        : "r"(a[0]), "r"(a[1]), "r"(a[2]), "r"(a[3]), "r"(b[0]), "r"(b[1]));
}

// ---------------------------------------------------------------------------
// proj via mma.sync bf16 split: D = Ahi@Whi + Ahi@Wlo + Alo@Whi (f32 accum)
// ---------------------------------------------------------------------------
__global__ __launch_bounds__(256)
void proj_mma_kernel(const float* __restrict__ raw,
                     const float* __restrict__ Wf,
                     const float* __restrict__ bf)
{
    extern __shared__ char sm[];
    __shared__ float bf_sh[D_DIM];

    const int tid  = threadIdx.x;
    const int warp = tid >> 5;
    const int lane = tid & 31;
    const int rowBase = blockIdx.x * ROWS_PB;

    if (tid < D_DIM) bf_sh[tid] = bf[tid];

    // ---- W staging: Wf[k][n] f32 -> Wsh[n][k] bf16 hi/lo (one-time, 16/thr) ----
    #pragma unroll
    for (int j = 0; j < (F_DIM * D_DIM) / 256; j++) {
        int e = tid + j * 256;          // linear = k*32 + n
        int k = e >> 5, n = e & 31;
        float x = Wf[e];
        __nv_bfloat16 h = __float2bfloat16(x);
        float hf = __bfloat162float(h);
        __nv_bfloat16 l = __float2bfloat16(x - hf);
        *reinterpret_cast<__nv_bfloat16*>(sm + SM_WHI + n * A_STRIDE + k * 2) = h;
        *reinterpret_cast<__nv_bfloat16*>(sm + SM_WLO + n * A_STRIDE + k * 2) = l;
    }

    // ---- A staging: 128 rows x 128 f32, coalesced LDG.128 -> bf16 hi/lo ----
    #pragma unroll
    for (int j = 0; j < (ROWS_PB * F_DIM / 4) / 256; j++) {   // 16 iters
        int i = tid + j * 256;              // float4 index
        int r = i >> 5, c4 = i & 31;        // row, float4-within-row
        int gr = rowBase + r;
        float4 v = make_float4(0.f, 0.f, 0.f, 0.f);
        if (gr < N_NODES)
            v = *reinterpret_cast<const float4*>(raw + (size_t)gr * F_DIM + c4 * 4);
        if (c4 == 0 && gr < N_NODES) g_skill[gr] = (int)v.x;

        uint32_t h0 = packbf(v.x, v.y);
        uint32_t h1 = packbf(v.z, v.w);
        float hx = __uint_as_float(h0 << 16);
        float hy = __uint_as_float(h0 & 0xffff0000u);
        float hz = __uint_as_float(h1 << 16);
        float hw = __uint_as_float(h1 & 0xffff0000u);
        uint32_t l0 = packbf(v.x - hx, v.y - hy);
        uint32_t l1 = packbf(v.z - hz, v.w - hw);

        uint32_t off = (uint32_t)r * A_STRIDE + c4 * 8;   // 4 bf16 = 8B
        *reinterpret_cast<uint2*>(sm + SM_AHI + off) = make_uint2(h0, h1);
        *reinterpret_cast<uint2*>(sm + SM_ALO + off) = make_uint2(l0, l1);
    }
    __syncthreads();

    // ---- MMA: warp w handles rows [w*16, w*16+16), all 32 output cols ----
    const int r0 = warp * 16 + (lane >> 2);       // fragment row (and +8)
    const int kb = ((lane & 3) * 2) * 2;          // fragment k byte offset

    float acc[4][4];
    #pragma unroll
    for (int t = 0; t < 4; t++)
        #pragma unroll
        for (int q = 0; q < 4; q++) acc[t][q] = 0.f;

    #pragma unroll
    for (int s = 0; s < 8; s++) {
        const int kob = s * 32;                   // 16 k * 2B per step
        uint32_t ahi[4], alo[4];
        {
            const char* pa = sm + SM_AHI + (uint32_t)r0 * A_STRIDE + kob + kb;
            const char* pb = sm + SM_AHI + (uint32_t)(r0 + 8) * A_STRIDE + kob + kb;
            ahi[0] = *reinterpret_cast<const uint32_t*>(pa);
            ahi[1] = *reinterpret_cast<const uint32_t*>(pb);
            ahi[2] = *reinterpret_cast<const uint32_t*>(pa + 16);
            ahi[3] = *reinterpret_cast<const uint32_t*>(pb + 16);
            const char* qa = sm + SM_ALO + (uint32_t)r0 * A_STRIDE + kob + kb;
            const char* qb = sm + SM_ALO + (uint32_t)(r0 + 8) * A_STRIDE + kob + kb;
            alo[0] = *reinterpret_cast<const uint32_t*>(qa);
            alo[1] = *reinterpret_cast<const uint32_t*>(qb);
            alo[2] = *reinterpret_cast<const uint32_t*>(qa + 16);
            alo[3] = *reinterpret_cast<const uint32_t*>(qb + 16);
        }
        #pragma unroll
        for (int t = 0; t < 4; t++) {
            const int n = t * 8 + (lane >> 2);
            const char* ph = sm + SM_WHI + (uint32_t)n * A_STRIDE + kob + kb;
            const char* pl = sm + SM_WLO + (uint32_t)n * A_STRIDE + kob + kb;
            uint32_t bh[2], bl[2];
            bh[0] = *reinterpret_cast<const uint32_t*>(ph);
            bh[1] = *reinterpret_cast<const uint32_t*>(ph + 16);
            bl[0] = *reinterpret_cast<const uint32_t*>(pl);
            bl[1] = *reinterpret_cast<const uint32_t*>(pl + 16);
            mma16816(acc[t], ahi, bh);
            mma16816(acc[t], ahi, bl);
            mma16816(acc[t], alo, bh);
        }
    }

    // ---- store D + bias ----
    const int rowA = rowBase + r0;
    const int rowB = rowA + 8;
    #pragma unroll
    for (int t = 0; t < 4; t++) {
        const int col = t * 8 + (lane & 3) * 2;
        const float b0 = bf_sh[col], b1 = bf_sh[col + 1];
        if (rowA < N_NODES)
            *reinterpret_cast<float2*>(g_proj + (size_t)rowA * D_DIM + col)
                = make_float2(acc[t][0] + b0, acc[t][1] + b1);
        if (rowB < N_NODES)
            *reinterpret_cast<float2*>(g_proj + (size_t)rowB * D_DIM + col)
                = make_float2(acc[t][2] + b0, acc[t][3] + b1);
    }
}

// ---------------------------------------------------------------------------
// Per-batch fused pipeline (unchanged from R7 best — 36.7us)
// ---------------------------------------------------------------------------
__global__ __launch_bounds__(256)
void main_kernel(const int* __restrict__ retrieved_nodes,
                 const int* __restrict__ retrieved_indices,
                 const int* __restrict__ dst_node_ids,
                 const float* __restrict__ w_struct, const float* __restrict__ b_struct,
                 const float* __restrict__ ln_g,    const float* __restrict__ ln_b,
                 const float* __restrict__ W_gcn,   const float* __restrict__ b_gcn,
                 const float* __restrict__ W_out,   const float* __restrict__ b_out,
                 float* __restrict__ out)
{
    __shared__ float hist[L_SEQ][D_DIM];
    __shared__ float xw[L_SEQ][D_DIM];
    __shared__ float ws[D_DIM], bs[D_DIM], lg[D_DIM], lb[D_DIM], bg[D_DIM];
    __shared__ float partial[8][D_DIM];
    __shared__ float dstfeat[D_DIM];
    __shared__ int   nodes_sh[R_RET][L_SEQ];
    __shared__ int   pidx[R_RET];
    __shared__ int   validsh;
    __shared__ int   curskill;

    const int b = blockIdx.x;
    const int tid = threadIdx.x;
    const int warp = tid >> 5;
    const int lane = tid & 31;

    if (tid < D_DIM) {
        ws[tid] = w_struct[tid]; bs[tid] = b_struct[tid];
        lg[tid] = ln_g[tid];     lb[tid] = ln_b[tid];
        bg[tid] = b_gcn[tid];
    }
    if (tid < R_RET) pidx[tid] = retrieved_indices[b * R_RET + tid];
    if (tid == 0) {
        validsh = 0;
        curskill = g_skill[dst_node_ids[b]];
    }
    if (tid >= 32 && tid < 64)
        dstfeat[tid - 32] = g_proj[(size_t)dst_node_ids[b] * D_DIM + (tid - 32)];
    __syncthreads();

    if (warp < R_RET) {
        const int* src = retrieved_nodes + (size_t)pidx[warp] * L_SEQ;
        for (int l = lane; l < L_SEQ; l += 32) nodes_sh[warp][l] = src[l];
    }
    __syncthreads();

    if (tid < L_SEQ && nodes_sh[0][tid] > 0) atomicAdd(&validsh, 1);

    const int cs = curskill;
    const float wsl = ws[lane], bsl = bs[lane], lgl = lg[lane], lbl = lb[lane];

    auto layernorm = [&](float val) -> float {
        float s1 = val, s2 = val * val;
        #pragma unroll
        for (int o = 16; o; o >>= 1) {
            s1 += __shfl_xor_sync(0xffffffffu, s1, o);
            s2 += __shfl_xor_sync(0xffffffffu, s2, o);
        }
        float mean = s1 * (1.f / 32.f);
        float var  = s2 * (1.f / 32.f) - mean * mean;
        return (val - mean) * rsqrtf(var + 1e-5f) * lgl + lbl;
    };

    for (int l0 = warp; l0 < L_SEQ; l0 += 16) {
        const int l1 = l0 + 8;
        const bool has1 = (l1 < L_SEQ);

        float p0[R_RET], p1[R_RET];
        int   s0[R_RET], s1i[R_RET];
        #pragma unroll
        for (int r = 0; r < R_RET; r++) {
            int n = nodes_sh[r][l0];
            p0[r] = g_proj[(size_t)n * D_DIM + lane];
            s0[r] = g_skill[n];
        }
        if (has1) {
            #pragma unroll
            for (int r = 0; r < R_RET; r++) {
                int n = nodes_sh[r][l1];
                p1[r] = g_proj[(size_t)n * D_DIM + lane];
                s1i[r] = g_skill[n];
            }
        }
        {
            float s = p0[0] + p0[1] + p0[2] + p0[3] + p0[4];
            int simc = (s0[0]==cs) + (s0[1]==cs) + (s0[2]==cs) + (s0[3]==cs) + (s0[4]==cs);
            float val = s * 0.2f + ((float)simc * 0.2f) * wsl + bsl;
            hist[l0][lane] = layernorm(val);
        }
        if (has1) {
            float s = p1[0] + p1[1] + p1[2] + p1[3] + p1[4];
            int simc = (s1i[0]==cs) + (s1i[1]==cs) + (s1i[2]==cs) + (s1i[3]==cs) + (s1i[4]==cs);
            float val = s * 0.2f + ((float)simc * 0.2f) * wsl + bsl;
            hist[l1][lane] = layernorm(val);
        }
    }

    float wreg[D_DIM];
    #pragma unroll
    for (int k = 0; k < D_DIM; k++) wreg[k] = W_gcn[k * D_DIM + lane];

    __syncthreads();
    const int valid = validsh;

    for (int l = warp; l < L_SEQ; l += 8) {
        const float4* hp = reinterpret_cast<const float4*>(hist[l]);
        float acc = 0.f;
        #pragma unroll
        for (int q = 0; q < 8; q++) {
            float4 h = hp[q];
            acc = fmaf(h.x, wreg[4 * q + 0], acc);
            acc = fmaf(h.y, wreg[4 * q + 1], acc);
            acc = fmaf(h.z, wreg[4 * q + 2], acc);
            acc = fmaf(h.w, wreg[4 * q + 3], acc);
        }
        xw[l][lane] = acc;
    }
    __syncthreads();

    const float bgl = bg[lane];
    float pacc = 0.f;
    for (int l = warp; l < L_SEQ; l += 8) {
        float degl = (l >= 1 && l < valid) ? 2.f : 1.f;
        float o = xw[l][lane] / degl;
        if (l >= 1 && l < valid) {
            float degp = (l - 1 >= 1 && (l - 1) < valid) ? 2.f : 1.f;
            o += xw[l - 1][lane] * rsqrtf(degp * degl);
        }
        o += bgl;
        pacc += fmaxf(o, 0.f);
    }
    partial[warp][lane] = pacc;
    __syncthreads();

    if (warp == 0) {
        float p = 0.f;
        #pragma unroll
        for (int w = 0; w < 8; w++) p += partial[w][lane];
        partial[0][lane] = p * (1.f / (float)L_SEQ);
    }
    __syncthreads();

    if (warp == 0) {
        float acc = b_out[lane];
        #pragma unroll
        for (int k = 0; k < D_DIM; k++)
            acc = fmaf(partial[0][k], W_out[k * D_DIM + lane], acc);
        out[b * D_DIM + lane] = acc;
    } else if (warp == 1) {
        float acc = b_out[lane];
        #pragma unroll
        for (int k = 0; k < D_DIM; k++)
            acc = fmaf(dstfeat[k], W_out[k * D_DIM + lane], acc);
        out[B_BATCH * D_DIM + b * D_DIM + lane] = acc;
    }
}

// ---------------------------------------------------------------------------
extern "C" void kernel_launch(void* const* d_in, const int* in_sizes, int n_in,
                              void* d_out, int out_size)
{
    const float* raw      = (const float*)d_in[0];
    const int*   rnodes   = (const int*)  d_in[1];
    const int*   rindices = (const int*)  d_in[2];
    const int*   dst_ids  = (const int*)  d_in[4];
    const float* W_feat   = (const float*)d_in[6];
    const float* b_feat   = (const float*)d_in[7];
    const float* w_struct = (const float*)d_in[8];
    const float* b_struct = (const float*)d_in[9];
    const float* ln_g     = (const float*)d_in[10];
    const float* ln_b     = (const float*)d_in[11];
    const float* W_gcn    = (const float*)d_in[12];
    const float* b_gcn    = (const float*)d_in[13];
    const float* W_out    = (const float*)d_in[14];
    const float* b_out    = (const float*)d_in[15];
    float* out = (float*)d_out;

    static int attr_set = 0;
    if (!attr_set) {
        cudaFuncSetAttribute(proj_mma_kernel,
                             cudaFuncAttributeMaxDynamicSharedMemorySize, SM_DYN);
        attr_set = 1;
    }
    proj_mma_kernel<<<N_PBLK, 256, SM_DYN>>>(raw, W_feat, b_feat);
    main_kernel<<<B_BATCH, 256>>>(rnodes, rindices, dst_ids,
                                  w_struct, b_struct, ln_g, ln_b,
                                  W_gcn, b_gcn, W_out, b_out, out);
}